// round 4
// baseline (speedup 1.0000x reference)
#include <cuda_runtime.h>

#define BB 8
#define HH 256
#define KK 256
#define EE 128
#define KT 16                  // keys per scores ktile
#define NKT (KK / KT)          // 16
#define HQ 4                   // head-quads in scores
#define HT (HH / HQ)           // 64 heads per scores CTA

#define VROWS 1000             // value_emb rows
#define ESL 32                 // e-slice width in agg
#define NESL (EE / ESL)        // 4
#define NG 38                  // agg groups: 4*38 = 152 CTAs = 1 wave on GB300
#define NPAIR (BB * HH)        // 2048
#define PPC 54                 // pairs per agg CTA (38*54 = 2052 >= 2048)

__device__ float g_delta[BB * HH * KK];   // exp(u)  (2 MB)
__device__ float g_o[NPAIR * EE];         // per-head outputs (1 MB)

// ---------------- Kernel A: scores ----------------
// grid (NKT, HQ, BB), 256 threads. CTA computes 64 h x 16 k.
// thread: hl = t&63, kq = t>>6 (4 keys). All compute reads from smem.
__global__ __launch_bounds__(256)
void kvmem_scores(const float* __restrict__ hidden,
                  const float* __restrict__ key_emb,
                  const int*   __restrict__ key_seq)
{
    const int kt = blockIdx.x;
    const int hq = blockIdx.y;
    const int b  = blockIdx.z;
    const int t  = threadIdx.x;
    const int hl = t & 63;
    const int kq = t >> 6;

    __shared__ float4 s_key[KT][32];       // 8 KB
    __shared__ float4 s_hidT[32][65];      // [e4][hl], padded: 33.3 KB

    // stage 16 key rows (gather, coalesced float4 per row)
    for (int i = t; i < KT * 32; i += 256) {
        int k  = i >> 5;
        int e4 = i & 31;
        int row = key_seq[b * KK + kt * KT + k];
        s_key[k][e4] = ((const float4*)(key_emb + (size_t)row * EE))[e4];
    }
    // stage hidden tile transposed (coalesced gmem read, conflict-free smem write)
    float* s_hidTf = (float*)s_hidT;
    for (int i = t; i < HT * EE; i += 256) {
        int r = i >> 7;
        int e = i & 127;
        float v = hidden[((size_t)b * HH + hq * HT + r) * EE + e];
        s_hidTf[(e >> 2) * 260 + r * 4 + (e & 3)] = v;
    }
    __syncthreads();

    float acc0 = 0.f, acc1 = 0.f, acc2 = 0.f, acc3 = 0.f;
    #pragma unroll 8
    for (int e4 = 0; e4 < 32; e4++) {
        float4 hv  = s_hidT[e4][hl];          // conflict-free LDS.128
        float4 kv0 = s_key[kq * 4 + 0][e4];   // broadcast
        float4 kv1 = s_key[kq * 4 + 1][e4];
        float4 kv2 = s_key[kq * 4 + 2][e4];
        float4 kv3 = s_key[kq * 4 + 3][e4];
        acc0 = fmaf(hv.x, kv0.x, acc0); acc0 = fmaf(hv.y, kv0.y, acc0);
        acc0 = fmaf(hv.z, kv0.z, acc0); acc0 = fmaf(hv.w, kv0.w, acc0);
        acc1 = fmaf(hv.x, kv1.x, acc1); acc1 = fmaf(hv.y, kv1.y, acc1);
        acc1 = fmaf(hv.z, kv1.z, acc1); acc1 = fmaf(hv.w, kv1.w, acc1);
        acc2 = fmaf(hv.x, kv2.x, acc2); acc2 = fmaf(hv.y, kv2.y, acc2);
        acc2 = fmaf(hv.z, kv2.z, acc2); acc2 = fmaf(hv.w, kv2.w, acc2);
        acc3 = fmaf(hv.x, kv3.x, acc3); acc3 = fmaf(hv.y, kv3.y, acc3);
        acc3 = fmaf(hv.z, kv3.z, acc3); acc3 = fmaf(hv.w, kv3.w, acc3);
    }

    const float inv_scale = 0.08838834764831845f;   // 1/sqrt(128)
    float4 ov;
    ov.x = expf(acc0 * inv_scale);
    ov.y = expf(acc1 * inv_scale);
    ov.z = expf(acc2 * inv_scale);
    ov.w = expf(acc3 * inv_scale);
    *((float4*)(g_delta + ((size_t)b * HH + hq * HT + hl) * KK + kt * KT + kq * 4)) = ov;
}

// ---------------- Kernel B: aggregation with smem-resident value slice ----------------
// grid (NESL, NG) = 152 CTAs (1 wave), 256 threads, dynamic smem ~141 KB.
// CTA stages value_emb[:, eq*32:+32] into smem; each warp processes heads
// independently: warp-local ballot compaction + shuffle-broadcast gather.
__global__ __launch_bounds__(256)
void kvmem_agg(const float* __restrict__ value_emb,
               const int*   __restrict__ value_seq,
               const int*   __restrict__ mask)
{
    extern __shared__ float dyn[];
    float* s_val = dyn;                                 // VROWS*ESL floats (128000 B)
    float* s_pc  = dyn + VROWS * ESL;                   // 8*256 floats
    int*   s_vl  = (int*)(s_pc + 8 * 256);              // 8*256 ints

    const int eq  = blockIdx.x;
    const int g   = blockIdx.y;
    const int t   = threadIdx.x;
    const int w   = t >> 5;
    const int lid = t & 31;

    // stage value slice (coalesced 128B per warp-read; conflict-free smem write)
    for (int i = t; i < VROWS * ESL; i += 256) {
        int r = i >> 5;
        int c = i & 31;
        s_val[i] = value_emb[(size_t)r * EE + eq * ESL + c];
    }
    __syncthreads();

    float* pc = s_pc + w * 256;
    int*   vl = s_vl + w * 256;

    for (int pp = w; pp < PPC; pp += 8) {
        int pi = g * PPC + pp;
        if (pi >= NPAIR) break;
        const int base = pi * KK;

        // masked delta -> warp-local compaction (deterministic order)
        float dsum = 0.f;
        int n = 0;
        #pragma unroll
        for (int c = 0; c < 8; c++) {
            int k = c * 32 + lid;
            float d = g_delta[base + k] * (float)mask[base + k];
            dsum += d;
            unsigned bal = __ballot_sync(0xffffffffu, d > 0.f);
            if (d > 0.f) {
                int pos = n + __popc(bal & ((1u << lid) - 1u));
                pc[pos] = d;
                vl[pos] = value_seq[base + k];
            }
            n += __popc(bal);
        }
        #pragma unroll
        for (int m = 16; m > 0; m >>= 1)
            dsum += __shfl_xor_sync(0xffffffffu, dsum, m);
        const float inv = 1.0f / (dsum + 1e-10f);

        // gather from smem value slice; lane owns e = eq*32 + lid
        float acc = 0.f;
        for (int i0 = 0; i0 < n; i0 += 32) {
            float pk_l = pc[i0 + lid];      // values beyond n unused
            int   r_l  = vl[i0 + lid];
            int m = n - i0; if (m > 32) m = 32;
            #pragma unroll 8
            for (int j = 0; j < m; j++) {
                float pk = __shfl_sync(0xffffffffu, pk_l, j);
                int   r  = __shfl_sync(0xffffffffu, r_l, j);
                acc = fmaf(pk, s_val[r * ESL + lid], acc);   // conflict-free
            }
        }
        g_o[(size_t)pi * EE + eq * ESL + lid] = acc * inv;   // 0 stays exactly 0
    }
}

// ---------------- Kernel C: H-reduction with nonzero count ----------------
__global__ __launch_bounds__(256)
void kvmem_reduce(float* __restrict__ out)
{
    const int eq  = blockIdx.x;           // 0..3
    const int b   = blockIdx.y;
    const int t   = threadIdx.x;
    const int w   = t >> 5;
    const int lid = t & 31;

    float sum = 0.f, cnt = 0.f;
    for (int hh = w; hh < HH; hh += 8) {
        float v = g_o[((size_t)b * HH + hh) * EE + eq * 32 + lid];
        sum += v;
        cnt += (v != 0.f) ? 1.f : 0.f;
    }

    __shared__ float s_s[8][32];
    __shared__ float s_c[8][32];
    s_s[w][lid] = sum;
    s_c[w][lid] = cnt;
    __syncthreads();
    if (w == 0) {
        float S = 0.f, C = 0.f;
        #pragma unroll
        for (int j = 0; j < 8; j++) { S += s_s[j][lid]; C += s_c[j][lid]; }
        out[b * EE + eq * 32 + lid] = S / C;   // reference adds no epsilon here
    }
}

extern "C" void kernel_launch(void* const* d_in, const int* in_sizes, int n_in,
                              void* d_out, int out_size)
{
    const float* hidden    = (const float*)d_in[0];
    const float* key_emb   = (const float*)d_in[1];
    const float* value_emb = (const float*)d_in[2];
    const int*   key_seq   = (const int*)d_in[3];
    const int*   value_seq = (const int*)d_in[4];
    const int*   mask      = (const int*)d_in[5];
    float* out = (float*)d_out;

    const int agg_smem = (VROWS * ESL + 8 * 256 + 8 * 256) * 4;   // 144384 B
    cudaFuncSetAttribute(kvmem_agg, cudaFuncAttributeMaxDynamicSharedMemorySize, agg_smem);

    kvmem_scores<<<dim3(NKT, HQ, BB), 256>>>(hidden, key_emb, key_seq);
    kvmem_agg<<<dim3(NESL, NG), 256, agg_smem>>>(value_emb, value_seq, mask);
    kvmem_reduce<<<dim3(4, BB), 256>>>(out);
}

// round 7
// speedup vs baseline: 1.6175x; 1.6175x over previous
#include <cuda_runtime.h>

#define BB 8
#define HH 256
#define KK 256
#define EE 128

__device__ float g_hidT[BB * EE * HH];    // [b][e][h]  1 MB
__device__ float g_keyT[BB * EE * KK];    // [b][e][k]  1 MB (gathered key rows, transposed)
__device__ float g_delta[BB * HH * KK];   // masked exp(u)  2 MB
__device__ float g_o[BB * HH * EE];       // per-head outputs 1 MB

// ---------------- Kernel 0: gather + transpose ----------------
// grid (4 rtiles of 64, BB, 2 which), 256 threads. Conflict-free 129-pad transpose.
__global__ __launch_bounds__(256)
void kvmem_xpose(const float* __restrict__ hidden,
                 const float* __restrict__ key_emb,
                 const int*   __restrict__ key_seq)
{
    const int rt    = blockIdx.x;        // 64-row tile
    const int b     = blockIdx.y;
    const int which = blockIdx.z;        // 0: hidden, 1: keys
    const int t     = threadIdx.x;
    const int r0    = rt * 64;

    __shared__ float s[64 * 129];

    // stage: coalesced along e; smem writes conflict-free (banks follow e)
    for (int i = t; i < 64 * EE; i += 256) {
        int r = i >> 7;
        int e = i & 127;
        float v;
        if (which == 0) {
            v = hidden[((size_t)b * HH + r0 + r) * EE + e];
        } else {
            int row = key_seq[b * KK + r0 + r];
            v = key_emb[(size_t)row * EE + e];
        }
        s[r * 129 + e] = v;
    }
    __syncthreads();

    float* dst = (which == 0 ? g_hidT : g_keyT);
    // out: coalesced along r; smem reads conflict-free ((r+e) mod 32 distinct)
    for (int i = t; i < 64 * EE; i += 256) {
        int e = i >> 6;
        int r = i & 63;
        dst[((size_t)b * EE + e) * HH + r0 + r] = s[r * 129 + e];
    }
}

// ---------------- Kernel 1: scores (register-blocked GEMM) ----------------
// grid (4 ktiles of 64, 8 htiles of 32, BB), 128 threads.
// thread (tx=t&15 -> 4 k, ty=t>>4 -> 4 h): 4x4 fp32 accumulators.
__global__ __launch_bounds__(128)
void kvmem_scores(const int* __restrict__ mask)
{
    const int kt = blockIdx.x;
    const int ht = blockIdx.y;
    const int b  = blockIdx.z;
    const int k0 = kt * 64;
    const int h0 = ht * 32;
    const int t  = threadIdx.x;
    const int tx = t & 15;
    const int ty = t >> 4;

    __shared__ float4 s_hid[EE * 8];      // [e][h4]  16 KB
    __shared__ float4 s_key[EE * 16];     // [e][k4]  32 KB

    // stage (coalesced float4 gmem reads; conflict-free STS.128)
    const float4* hsrc = (const float4*)(g_hidT + (size_t)b * EE * HH);
    const float4* ksrc = (const float4*)(g_keyT + (size_t)b * EE * KK);
    #pragma unroll
    for (int i = t; i < EE * 8; i += 128) {
        int e  = i >> 3;
        int h4 = i & 7;
        s_hid[i] = hsrc[e * (HH / 4) + (h0 >> 2) + h4];
    }
    #pragma unroll
    for (int i = t; i < EE * 16; i += 128) {
        int e  = i >> 4;
        int k4 = i & 15;
        s_key[i] = ksrc[e * (KK / 4) + (k0 >> 2) + k4];
    }
    __syncthreads();

    float a00=0,a01=0,a02=0,a03=0, a10=0,a11=0,a12=0,a13=0;
    float a20=0,a21=0,a22=0,a23=0, a30=0,a31=0,a32=0,a33=0;

    #pragma unroll 4
    for (int e = 0; e < EE; e++) {
        float4 hv = s_hid[e * 8 + ty];    // 2 distinct/warp: broadcast
        float4 kv = s_key[e * 16 + tx];   // 16 distinct/warp: conflict-free
        a00 = fmaf(hv.x, kv.x, a00); a01 = fmaf(hv.x, kv.y, a01);
        a02 = fmaf(hv.x, kv.z, a02); a03 = fmaf(hv.x, kv.w, a03);
        a10 = fmaf(hv.y, kv.x, a10); a11 = fmaf(hv.y, kv.y, a11);
        a12 = fmaf(hv.y, kv.z, a12); a13 = fmaf(hv.y, kv.w, a13);
        a20 = fmaf(hv.z, kv.x, a20); a21 = fmaf(hv.z, kv.y, a21);
        a22 = fmaf(hv.z, kv.z, a22); a23 = fmaf(hv.z, kv.w, a23);
        a30 = fmaf(hv.w, kv.x, a30); a31 = fmaf(hv.w, kv.y, a31);
        a32 = fmaf(hv.w, kv.z, a32); a33 = fmaf(hv.w, kv.w, a33);
    }

    const float sc = 0.08838834764831845f;   // 1/sqrt(128)
    float r0c[4] = {a00,a01,a02,a03}, r1c[4] = {a10,a11,a12,a13};
    float r2c[4] = {a20,a21,a22,a23}, r3c[4] = {a30,a31,a32,a33};
    float* rows[4] = {r0c, r1c, r2c, r3c};

    #pragma unroll
    for (int jh = 0; jh < 4; jh++) {
        int h = h0 + ty * 4 + jh;
        size_t base = ((size_t)b * HH + h) * KK + k0 + tx * 4;
        int4 m = *((const int4*)(mask + base));
        float4 ov;
        ov.x = m.x ? expf(rows[jh][0] * sc) : 0.0f;
        ov.y = m.y ? expf(rows[jh][1] * sc) : 0.0f;
        ov.z = m.z ? expf(rows[jh][2] * sc) : 0.0f;
        ov.w = m.w ? expf(rows[jh][3] * sc) : 0.0f;
        *((float4*)(g_delta + base)) = ov;   // masked delta
    }
}

// ---------------- Kernel 2: normalize + value aggregation (round-3 shape) ----------------
// grid (HH, BB) = 2048 CTAs, 128 threads; thread t owns output column e=t.
__global__ __launch_bounds__(128)
void kvmem_agg(const float* __restrict__ value_emb,
               const int*   __restrict__ value_seq)
{
    const int h   = blockIdx.x;
    const int b   = blockIdx.y;
    const int t   = threadIdx.x;
    const int w   = t >> 5;
    const int lid = t & 31;
    const int base = (b * HH + h) * KK;

    __shared__ float s_d[KK];
    __shared__ int   s_vidx[KK];
    __shared__ float s_pc[KK];
    __shared__ int   s_vl[KK];
    __shared__ float s_red[4];
    __shared__ int   s_cnt[8];
    __shared__ int   s_basec[8];
    __shared__ float s_invv;
    __shared__ int   s_n;

    float part = 0.f;
    #pragma unroll
    for (int k = t; k < KK; k += 128) {
        float d = g_delta[base + k];          // already masked
        s_d[k] = d;
        s_vidx[k] = value_seq[base + k];
        part += d;
    }
    #pragma unroll
    for (int m = 16; m > 0; m >>= 1)
        part += __shfl_xor_sync(0xffffffffu, part, m);
    if (lid == 0) s_red[w] = part;
    __syncthreads();
    if (t == 0)
        s_invv = 1.0f / (s_red[0] + s_red[1] + s_red[2] + s_red[3] + 1e-10f);
    __syncthreads();
    const float inv = s_invv;

    // ballot compaction: 8 chunks of 32; warp w handles chunks 2w, 2w+1
    unsigned bal[2];
    #pragma unroll
    for (int c2 = 0; c2 < 2; c2++) {
        int c = 2 * w + c2;
        float d = s_d[c * 32 + lid];
        bal[c2] = __ballot_sync(0xffffffffu, d > 0.f);
        if (lid == 0) s_cnt[c] = __popc(bal[c2]);
    }
    __syncthreads();
    if (t == 0) {
        int run = 0;
        #pragma unroll
        for (int c = 0; c < 8; c++) { s_basec[c] = run; run += s_cnt[c]; }
        s_n = run;
    }
    __syncthreads();
    #pragma unroll
    for (int c2 = 0; c2 < 2; c2++) {
        int c = 2 * w + c2;
        int k = c * 32 + lid;
        float d = s_d[k];
        if (d > 0.f) {
            int pos = s_basec[c] + __popc(bal[c2] & ((1u << lid) - 1u));
            s_pc[pos] = d * inv;
            s_vl[pos] = s_vidx[k];
        }
    }
    __syncthreads();

    const int n = s_n;
    float acc = 0.f;
    int i = 0;
    for (; i + 8 <= n; i += 8) {
        #pragma unroll
        for (int j = 0; j < 8; j++)
            acc = fmaf(s_pc[i + j],
                       __ldg(value_emb + (size_t)s_vl[i + j] * EE + t), acc);
    }
    for (; i < n; i++)
        acc = fmaf(s_pc[i], __ldg(value_emb + (size_t)s_vl[i] * EE + t), acc);

    g_o[((size_t)b * HH + h) * EE + t] = acc;
}

// ---------------- Kernel 3: H-reduction with nonzero count ----------------
__global__ __launch_bounds__(256)
void kvmem_reduce(float* __restrict__ out)
{
    const int eq  = blockIdx.x;
    const int b   = blockIdx.y;
    const int t   = threadIdx.x;
    const int w   = t >> 5;
    const int lid = t & 31;

    float sum = 0.f, cnt = 0.f;
    for (int hh = w; hh < HH; hh += 8) {
        float v = g_o[((size_t)b * HH + hh) * EE + eq * 32 + lid];
        sum += v;
        cnt += (v != 0.f) ? 1.f : 0.f;
    }

    __shared__ float s_s[8][32];
    __shared__ float s_c[8][32];
    s_s[w][lid] = sum;
    s_c[w][lid] = cnt;
    __syncthreads();
    if (w == 0) {
        float S = 0.f, C = 0.f;
        #pragma unroll
        for (int j = 0; j < 8; j++) { S += s_s[j][lid]; C += s_c[j][lid]; }
        out[b * EE + eq * 32 + lid] = S / C;
    }
}

extern "C" void kernel_launch(void* const* d_in, const int* in_sizes, int n_in,
                              void* d_out, int out_size)
{
    const float* hidden    = (const float*)d_in[0];
    const float* key_emb   = (const float*)d_in[1];
    const float* value_emb = (const float*)d_in[2];
    const int*   key_seq   = (const int*)d_in[3];
    const int*   value_seq = (const int*)d_in[4];
    const int*   mask      = (const int*)d_in[5];
    float* out = (float*)d_out;

    kvmem_xpose<<<dim3(4, BB, 2), 256>>>(hidden, key_emb, key_seq);
    kvmem_scores<<<dim3(4, 8, BB), 128>>>(mask);
    kvmem_agg<<<dim3(HH, BB), 128>>>(value_emb, value_seq);
    kvmem_reduce<<<dim3(4, BB), 256>>>(out);
}

// round 8
// speedup vs baseline: 1.6690x; 1.0318x over previous
#include <cuda_runtime.h>

#define BB 8
#define HH 256
#define KK 256
#define EE 128

__device__ float g_hidT[BB * EE * HH];    // [b][e][h]  1 MB
__device__ float g_keyT[BB * EE * KK];    // [b][e][k]  1 MB (gathered key rows, transposed)
__device__ float g_delta[BB * HH * KK];   // masked exp(u)  2 MB
__device__ float g_sum[BB * EE];          // atomic H-sums
__device__ float g_cnt[BB * EE];          // atomic nonzero counts

// ---------------- Kernel 0: gather + transpose ----------------
__global__ __launch_bounds__(256)
void kvmem_xpose(const float* __restrict__ hidden,
                 const float* __restrict__ key_emb,
                 const int*   __restrict__ key_seq)
{
    const int rt    = blockIdx.x;        // 64-row tile
    const int b     = blockIdx.y;
    const int which = blockIdx.z;        // 0: hidden, 1: keys
    const int t     = threadIdx.x;
    const int r0    = rt * 64;

    __shared__ float s[64 * 129];

    for (int i = t; i < 64 * EE; i += 256) {
        int r = i >> 7;
        int e = i & 127;
        float v;
        if (which == 0) {
            v = hidden[((size_t)b * HH + r0 + r) * EE + e];
        } else {
            int row = key_seq[b * KK + r0 + r];
            v = key_emb[(size_t)row * EE + e];
        }
        s[r * 129 + e] = v;
    }
    __syncthreads();

    float* dst = (which == 0 ? g_hidT : g_keyT);
    for (int i = t; i < 64 * EE; i += 256) {
        int e = i >> 6;
        int r = i & 63;
        dst[((size_t)b * EE + e) * HH + r0 + r] = s[r * 129 + e];
    }
}

// ---------------- Kernel 1: scores (register-blocked GEMM) ----------------
// grid (4 ktiles of 64, 8 htiles of 32, BB), 128 threads; 4x4 accumulators.
// Also zeroes g_sum/g_cnt (CTA kt=0,ht=0 per b) before agg runs.
__global__ __launch_bounds__(128)
void kvmem_scores(const int* __restrict__ mask)
{
    const int kt = blockIdx.x;
    const int ht = blockIdx.y;
    const int b  = blockIdx.z;
    const int k0 = kt * 64;
    const int h0 = ht * 32;
    const int t  = threadIdx.x;
    const int tx = t & 15;
    const int ty = t >> 4;

    if (kt == 0 && ht == 0) {            // zero accumulators for this b
        g_sum[b * EE + t] = 0.0f;
        g_cnt[b * EE + t] = 0.0f;
    }

    __shared__ float4 s_hid[EE * 8];      // [e][h4]  16 KB
    __shared__ float4 s_key[EE * 16];     // [e][k4]  32 KB

    const float4* hsrc = (const float4*)(g_hidT + (size_t)b * EE * HH);
    const float4* ksrc = (const float4*)(g_keyT + (size_t)b * EE * KK);
    #pragma unroll
    for (int i = t; i < EE * 8; i += 128) {
        int e  = i >> 3;
        int h4 = i & 7;
        s_hid[i] = hsrc[e * (HH / 4) + (h0 >> 2) + h4];
    }
    #pragma unroll
    for (int i = t; i < EE * 16; i += 128) {
        int e  = i >> 4;
        int k4 = i & 15;
        s_key[i] = ksrc[e * (KK / 4) + (k0 >> 2) + k4];
    }
    __syncthreads();

    float a00=0,a01=0,a02=0,a03=0, a10=0,a11=0,a12=0,a13=0;
    float a20=0,a21=0,a22=0,a23=0, a30=0,a31=0,a32=0,a33=0;

    #pragma unroll 4
    for (int e = 0; e < EE; e++) {
        float4 hv = s_hid[e * 8 + ty];
        float4 kv = s_key[e * 16 + tx];
        a00 = fmaf(hv.x, kv.x, a00); a01 = fmaf(hv.x, kv.y, a01);
        a02 = fmaf(hv.x, kv.z, a02); a03 = fmaf(hv.x, kv.w, a03);
        a10 = fmaf(hv.y, kv.x, a10); a11 = fmaf(hv.y, kv.y, a11);
        a12 = fmaf(hv.y, kv.z, a12); a13 = fmaf(hv.y, kv.w, a13);
        a20 = fmaf(hv.z, kv.x, a20); a21 = fmaf(hv.z, kv.y, a21);
        a22 = fmaf(hv.z, kv.z, a22); a23 = fmaf(hv.z, kv.w, a23);
        a30 = fmaf(hv.w, kv.x, a30); a31 = fmaf(hv.w, kv.y, a31);
        a32 = fmaf(hv.w, kv.z, a32); a33 = fmaf(hv.w, kv.w, a33);
    }

    const float sc = 0.08838834764831845f;   // 1/sqrt(128)
    float r0c[4] = {a00,a01,a02,a03}, r1c[4] = {a10,a11,a12,a13};
    float r2c[4] = {a20,a21,a22,a23}, r3c[4] = {a30,a31,a32,a33};
    float* rows[4] = {r0c, r1c, r2c, r3c};

    #pragma unroll
    for (int jh = 0; jh < 4; jh++) {
        int h = h0 + ty * 4 + jh;
        size_t base = ((size_t)b * HH + h) * KK + k0 + tx * 4;
        int4 m = *((const int4*)(mask + base));
        float4 ov;
        ov.x = m.x ? expf(rows[jh][0] * sc) : 0.0f;
        ov.y = m.y ? expf(rows[jh][1] * sc) : 0.0f;
        ov.z = m.z ? expf(rows[jh][2] * sc) : 0.0f;
        ov.w = m.w ? expf(rows[jh][3] * sc) : 0.0f;
        *((float4*)(g_delta + base)) = ov;
    }
}

// ---------------- Kernel 2: normalize + aggregation + atomic H-reduce ----------------
// grid (HH, BB) = 2048 CTAs, 128 threads; thread t owns output column e=t.
__global__ __launch_bounds__(128)
void kvmem_agg(const float* __restrict__ value_emb,
               const int*   __restrict__ value_seq)
{
    const int h   = blockIdx.x;
    const int b   = blockIdx.y;
    const int t   = threadIdx.x;
    const int w   = t >> 5;
    const int lid = t & 31;
    const int base = (b * HH + h) * KK;

    __shared__ float s_d[KK];
    __shared__ int   s_vidx[KK];
    __shared__ float s_pc[KK];
    __shared__ int   s_vl[KK];
    __shared__ float s_red[4];
    __shared__ int   s_cnt[8];
    __shared__ int   s_basec[8];
    __shared__ float s_invv;
    __shared__ int   s_n;

    float part = 0.f;
    #pragma unroll
    for (int k = t; k < KK; k += 128) {
        float d = g_delta[base + k];          // already masked
        s_d[k] = d;
        s_vidx[k] = value_seq[base + k];
        part += d;
    }
    #pragma unroll
    for (int m = 16; m > 0; m >>= 1)
        part += __shfl_xor_sync(0xffffffffu, part, m);
    if (lid == 0) s_red[w] = part;
    __syncthreads();
    if (t == 0)
        s_invv = 1.0f / (s_red[0] + s_red[1] + s_red[2] + s_red[3] + 1e-10f);
    __syncthreads();
    const float inv = s_invv;

    unsigned bal[2];
    #pragma unroll
    for (int c2 = 0; c2 < 2; c2++) {
        int c = 2 * w + c2;
        float d = s_d[c * 32 + lid];
        bal[c2] = __ballot_sync(0xffffffffu, d > 0.f);
        if (lid == 0) s_cnt[c] = __popc(bal[c2]);
    }
    __syncthreads();
    if (t == 0) {
        int run = 0;
        #pragma unroll
        for (int c = 0; c < 8; c++) { s_basec[c] = run; run += s_cnt[c]; }
        s_n = run;
    }
    __syncthreads();
    #pragma unroll
    for (int c2 = 0; c2 < 2; c2++) {
        int c = 2 * w + c2;
        int k = c * 32 + lid;
        float d = s_d[k];
        if (d > 0.f) {
            int pos = s_basec[c] + __popc(bal[c2] & ((1u << lid) - 1u));
            s_pc[pos] = d * inv;
            s_vl[pos] = s_vidx[k];
        }
    }
    __syncthreads();

    const int n = s_n;
    float acc = 0.f;
    int i = 0;
    for (; i + 8 <= n; i += 8) {
        #pragma unroll
        for (int j = 0; j < 8; j++)
            acc = fmaf(s_pc[i + j],
                       __ldg(value_emb + (size_t)s_vl[i + j] * EE + t), acc);
    }
    for (; i < n; i++)
        acc = fmaf(s_pc[i], __ldg(value_emb + (size_t)s_vl[i] * EE + t), acc);

    // fused H-reduction via global atomics (cnt adds are exact)
    atomicAdd(&g_sum[b * EE + t], acc);
    if (acc != 0.0f)
        atomicAdd(&g_cnt[b * EE + t], 1.0f);
}

// ---------------- Kernel 3: tiny epilogue ----------------
__global__ __launch_bounds__(128)
void kvmem_final(float* __restrict__ out)
{
    const int b = blockIdx.x;
    const int t = threadIdx.x;
    out[b * EE + t] = g_sum[b * EE + t] / g_cnt[b * EE + t];  // ref has no epsilon
}

extern "C" void kernel_launch(void* const* d_in, const int* in_sizes, int n_in,
                              void* d_out, int out_size)
{
    const float* hidden    = (const float*)d_in[0];
    const float* key_emb   = (const float*)d_in[1];
    const float* value_emb = (const float*)d_in[2];
    const int*   key_seq   = (const int*)d_in[3];
    const int*   value_seq = (const int*)d_in[4];
    const int*   mask      = (const int*)d_in[5];
    float* out = (float*)d_out;

    kvmem_xpose<<<dim3(4, BB, 2), 256>>>(hidden, key_emb, key_seq);
    kvmem_scores<<<dim3(4, 8, BB), 128>>>(mask);
    kvmem_agg<<<dim3(HH, BB), 128>>>(value_emb, value_seq);
    kvmem_final<<<BB, EE>>>(out);
}

// round 10
// speedup vs baseline: 1.6857x; 1.0100x over previous
#include <cuda_runtime.h>

#define BB 8
#define HH 256
#define KK 256
#define EE 128

__device__ float g_hidT[BB * EE * HH];    // [b][e][h]  1 MB
__device__ float g_keyT[BB * EE * KK];    // [b][e][k]  1 MB (gathered key rows, transposed)
__device__ float g_delta[BB * HH * KK];   // masked exp(u)  2 MB
__device__ float g_sum[BB * EE];          // atomic H-sums
__device__ float g_cnt[BB * EE];          // atomic nonzero counts

// ---------------- Kernel 0: gather + transpose ----------------
__global__ __launch_bounds__(256)
void kvmem_xpose(const float* __restrict__ hidden,
                 const float* __restrict__ key_emb,
                 const int*   __restrict__ key_seq)
{
    const int rt    = blockIdx.x;        // 64-row tile
    const int b     = blockIdx.y;
    const int which = blockIdx.z;        // 0: hidden, 1: keys
    const int t     = threadIdx.x;
    const int r0    = rt * 64;

    __shared__ float s[64 * 129];

    for (int i = t; i < 64 * EE; i += 256) {
        int r = i >> 7;
        int e = i & 127;
        float v;
        if (which == 0) {
            v = hidden[((size_t)b * HH + r0 + r) * EE + e];
        } else {
            int row = key_seq[b * KK + r0 + r];
            v = key_emb[(size_t)row * EE + e];
        }
        s[r * 129 + e] = v;
    }
    __syncthreads();

    float* dst = (which == 0 ? g_hidT : g_keyT);
    for (int i = t; i < 64 * EE; i += 256) {
        int e = i >> 6;
        int r = i & 63;
        dst[((size_t)b * EE + e) * HH + r0 + r] = s[r * 129 + e];
    }
}

// ---------------- Kernel 1: scores (register-blocked GEMM) ----------------
// grid (4 ktiles of 64, 8 htiles of 32, BB), 128 threads; 4x4 accumulators.
// Also zeroes g_sum/g_cnt (CTA kt=0,ht=0 per b) before agg runs.
__global__ __launch_bounds__(128)
void kvmem_scores(const int* __restrict__ mask)
{
    const int kt = blockIdx.x;
    const int ht = blockIdx.y;
    const int b  = blockIdx.z;
    const int k0 = kt * 64;
    const int h0 = ht * 32;
    const int t  = threadIdx.x;
    const int tx = t & 15;
    const int ty = t >> 4;

    if (kt == 0 && ht == 0) {            // zero accumulators for this b
        g_sum[b * EE + t] = 0.0f;
        g_cnt[b * EE + t] = 0.0f;
    }

    __shared__ float4 s_hid[EE * 8];      // [e][h4]  16 KB
    __shared__ float4 s_key[EE * 16];     // [e][k4]  32 KB

    const float4* hsrc = (const float4*)(g_hidT + (size_t)b * EE * HH);
    const float4* ksrc = (const float4*)(g_keyT + (size_t)b * EE * KK);
    #pragma unroll
    for (int i = t; i < EE * 8; i += 128) {
        int e  = i >> 3;
        int h4 = i & 7;
        s_hid[i] = hsrc[e * (HH / 4) + (h0 >> 2) + h4];
    }
    #pragma unroll
    for (int i = t; i < EE * 16; i += 128) {
        int e  = i >> 4;
        int k4 = i & 15;
        s_key[i] = ksrc[e * (KK / 4) + (k0 >> 2) + k4];
    }
    __syncthreads();

    float a00=0,a01=0,a02=0,a03=0, a10=0,a11=0,a12=0,a13=0;
    float a20=0,a21=0,a22=0,a23=0, a30=0,a31=0,a32=0,a33=0;

    #pragma unroll 4
    for (int e = 0; e < EE; e++) {
        float4 hv = s_hid[e * 8 + ty];
        float4 kv = s_key[e * 16 + tx];
        a00 = fmaf(hv.x, kv.x, a00); a01 = fmaf(hv.x, kv.y, a01);
        a02 = fmaf(hv.x, kv.z, a02); a03 = fmaf(hv.x, kv.w, a03);
        a10 = fmaf(hv.y, kv.x, a10); a11 = fmaf(hv.y, kv.y, a11);
        a12 = fmaf(hv.y, kv.z, a12); a13 = fmaf(hv.y, kv.w, a13);
        a20 = fmaf(hv.z, kv.x, a20); a21 = fmaf(hv.z, kv.y, a21);
        a22 = fmaf(hv.z, kv.z, a22); a23 = fmaf(hv.z, kv.w, a23);
        a30 = fmaf(hv.w, kv.x, a30); a31 = fmaf(hv.w, kv.y, a31);
        a32 = fmaf(hv.w, kv.z, a32); a33 = fmaf(hv.w, kv.w, a33);
    }

    const float sc = 0.08838834764831845f;   // 1/sqrt(128)
    float r0c[4] = {a00,a01,a02,a03}, r1c[4] = {a10,a11,a12,a13};
    float r2c[4] = {a20,a21,a22,a23}, r3c[4] = {a30,a31,a32,a33};
    float* rows[4] = {r0c, r1c, r2c, r3c};

    #pragma unroll
    for (int jh = 0; jh < 4; jh++) {
        int h = h0 + ty * 4 + jh;
        size_t base = ((size_t)b * HH + h) * KK + k0 + tx * 4;
        int4 m = *((const int4*)(mask + base));
        float4 ov;
        ov.x = m.x ? expf(rows[jh][0] * sc) : 0.0f;
        ov.y = m.y ? expf(rows[jh][1] * sc) : 0.0f;
        ov.z = m.z ? expf(rows[jh][2] * sc) : 0.0f;
        ov.w = m.w ? expf(rows[jh][3] * sc) : 0.0f;
        *((float4*)(g_delta + base)) = ov;
    }
}

// ---------------- Kernel 2: normalize + aggregation + atomic H-reduce ----------------
// grid (HH, BB) = 2048 CTAs, 128 threads; thread t owns output column e=t.
__global__ __launch_bounds__(128)
void kvmem_agg(const float* __restrict__ value_emb,
               const int*   __restrict__ value_seq)
{
    const int h   = blockIdx.x;
    const int b   = blockIdx.y;
    const int t   = threadIdx.x;
    const int w   = t >> 5;
    const int lid = t & 31;
    const int base = (b * HH + h) * KK;

    __shared__ float s_d[KK];
    __shared__ int   s_vidx[KK];
    __shared__ float s_pc[KK];
    __shared__ int   s_vl[KK];
    __shared__ float s_red[4];
    __shared__ int   s_cnt[8];
    __shared__ int   s_basec[8];
    __shared__ float s_invv;
    __shared__ int   s_n;

    float part = 0.f;
    #pragma unroll
    for (int k = t; k < KK; k += 128) {
        float d = g_delta[base + k];          // already masked
        s_d[k] = d;
        s_vidx[k] = value_seq[base + k];
        part += d;
    }
    #pragma unroll
    for (int m = 16; m > 0; m >>= 1)
        part += __shfl_xor_sync(0xffffffffu, part, m);
    if (lid == 0) s_red[w] = part;
    __syncthreads();
    if (t == 0)
        s_invv = 1.0f / (s_red[0] + s_red[1] + s_red[2] + s_red[3] + 1e-10f);
    __syncthreads();
    const float inv = s_invv;

    unsigned bal[2];
    #pragma unroll
    for (int c2 = 0; c2 < 2; c2++) {
        int c = 2 * w + c2;
        float d = s_d[c * 32 + lid];
        bal[c2] = __ballot_sync(0xffffffffu, d > 0.f);
        if (lid == 0) s_cnt[c] = __popc(bal[c2]);
    }
    __syncthreads();
    if (t == 0) {
        int run = 0;
        #pragma unroll
        for (int c = 0; c < 8; c++) { s_basec[c] = run; run += s_cnt[c]; }
        s_n = run;
    }
    __syncthreads();
    #pragma unroll
    for (int c2 = 0; c2 < 2; c2++) {
        int c = 2 * w + c2;
        int k = c * 32 + lid;
        float d = s_d[k];
        if (d > 0.f) {
            int pos = s_basec[c] + __popc(bal[c2] & ((1u << lid) - 1u));
            s_pc[pos] = d * inv;
            s_vl[pos] = s_vidx[k];
        }
    }
    __syncthreads();

    const int n = s_n;
    float acc = 0.f;
    int i = 0;
    for (; i + 8 <= n; i += 8) {
        #pragma unroll
        for (int j = 0; j < 8; j++)
            acc = fmaf(s_pc[i + j],
                       __ldg(value_emb + (size_t)s_vl[i + j] * EE + t), acc);
    }
    for (; i < n; i++)
        acc = fmaf(s_pc[i], __ldg(value_emb + (size_t)s_vl[i] * EE + t), acc);

    // fused H-reduction via global atomics (cnt adds are exact)
    atomicAdd(&g_sum[b * EE + t], acc);
    if (acc != 0.0f)
        atomicAdd(&g_cnt[b * EE + t], 1.0f);
}

// ---------------- Kernel 3: tiny epilogue ----------------
__global__ __launch_bounds__(128)
void kvmem_final(float* __restrict__ out)
{
    const int b = blockIdx.x;
    const int t = threadIdx.x;
    out[b * EE + t] = g_sum[b * EE + t] / g_cnt[b * EE + t];  // ref has no epsilon
}

extern "C" void kernel_launch(void* const* d_in, const int* in_sizes, int n_in,
                              void* d_out, int out_size)
{
    const float* hidden    = (const float*)d_in[0];
    const float* key_emb   = (const float*)d_in[1];
    const float* value_emb = (const float*)d_in[2];
    const int*   key_seq   = (const int*)d_in[3];
    const int*   value_seq = (const int*)d_in[4];
    const int*   mask      = (const int*)d_in[5];
    float* out = (float*)d_out;

    kvmem_xpose<<<dim3(4, BB, 2), 256>>>(hidden, key_emb, key_seq);
    kvmem_scores<<<dim3(4, 8, BB), 128>>>(mask);
    kvmem_agg<<<dim3(HH, BB), 128>>>(value_emb, value_seq);
    kvmem_final<<<BB, EE>>>(out);
}